// round 5
// baseline (speedup 1.0000x reference)
#include <cuda_runtime.h>
#include <cuda_bf16.h>
#include <math.h>
#include <stdint.h>

#define B_ 32
#define T_ 2048
#define D_ 512
#define U_ 512
#define MT 65536            // B*T rows
#define MB_ 512             // M blocks of 128
#define NB_ 4               // N blocks of 128
#define KCH 8               // k chunks of 64
#define STAGES 2
#define KSPLIT 8
#define TILE_BYTES 16384    // 128 x 64 bf16

// ---------------- scratch (static device memory only) -----------------------
__device__ __align__(128) __nv_bfloat16 g_val_hi[MT * D_];
__device__ __align__(128) __nv_bfloat16 g_val_lo[MT * D_];
__device__ __align__(128) __nv_bfloat16 g_w1t_hi[U_ * D_];
__device__ __align__(128) __nv_bfloat16 g_w1t_lo[U_ * D_];
__device__ float g_bias_part[KSPLIT][B_ * U_];
__device__ float g_part[NB_][MT];

// ---------------- PTX helpers -----------------------------------------------
__device__ __forceinline__ uint32_t smem_u32(const void* p) {
    uint32_t a;
    asm("{ .reg .u64 t; cvta.to.shared.u64 t, %1; cvt.u32.u64 %0, t; }"
        : "=r"(a) : "l"(p));
    return a;
}
__device__ __forceinline__ uint32_t sw128(uint32_t off) {
    return off ^ ((off >> 3) & 0x70);
}
#define MBAR_INIT(a, n) \
    asm volatile("mbarrier.init.shared.b64 [%0], %1;" :: "r"(a), "r"(n) : "memory")
#define MBAR_ARRIVE(a) \
    asm volatile("mbarrier.arrive.shared.b64 _, [%0];" :: "r"(a) : "memory")
#define MBAR_EXPECT_TX(a, n) \
    asm volatile("mbarrier.arrive.expect_tx.shared.b64 _, [%0], %1;" \
                 :: "r"(a), "r"(n) : "memory")
#define MBAR_WAIT(a, ph) do {                                                  \
    uint32_t _m = (a), _p = (ph), _d;                                          \
    asm volatile("{ .reg .pred p; mbarrier.try_wait.parity.acquire.cta.shared::cta.b64 p, [%1], %2; selp.b32 %0,1,0,p; }" \
                 : "=r"(_d) : "r"(_m), "r"(_p) : "memory");                    \
    if (!_d) {                                                                 \
        asm volatile("{ .reg .pred P1; WL%=: mbarrier.try_wait.parity.acquire.cta.shared::cta.b64 P1, [%0], %1, 0x989680; @P1 bra.uni WD%=; bra.uni WL%=; WD%=: }" \
                     :: "r"(_m), "r"(_p) : "memory");                          \
    }                                                                          \
} while (0)
#define BULK_G2S(dst, src, bytes, mbar)                                        \
    asm volatile("cp.async.bulk.shared::cluster.global.mbarrier::complete_tx::bytes [%0], [%1], %2, [%3];" \
                 :: "r"(dst), "l"(src), "r"(bytes), "r"(mbar) : "memory")
#define LDSM4(r, addr)                                                         \
    asm volatile("ldmatrix.sync.aligned.m8n8.x4.shared.b16 {%0,%1,%2,%3}, [%4];" \
                 : "=r"((r)[0]), "=r"((r)[1]), "=r"((r)[2]), "=r"((r)[3])      \
                 : "r"(addr))
#define MMA16816(d, a, b)                                                      \
    asm volatile("mma.sync.aligned.m16n8k16.row.col.f32.bf16.bf16.f32 "        \
                 "{%0,%1,%2,%3}, {%4,%5,%6,%7}, {%8,%9}, {%0,%1,%2,%3};"       \
                 : "+f"((d)[0]), "+f"((d)[1]), "+f"((d)[2]), "+f"((d)[3])      \
                 : "r"((a)[0]), "r"((a)[1]), "r"((a)[2]), "r"((a)[3]),         \
                   "r"((b)[0]), "r"((b)[1]))

// tanh via exp: abs err ~1e-6; saturates correctly for large |x|
__device__ __forceinline__ float tanh_fast(float x) {
    float z = __expf(2.0f * x);
    return 1.0f - __fdividef(2.0f, z + 1.0f);
}

// ---------------- kernel 1a: value fp32 -> tiled swizzled bf16 hi/lo --------
__global__ void convert_value(const float4* __restrict__ v4) {
    char* dhi = reinterpret_cast<char*>(g_val_hi);
    char* dlo = reinterpret_cast<char*>(g_val_lo);
    const int ngran = MT * D_ / 8;
    for (int i = blockIdx.x * blockDim.x + threadIdx.x; i < ngran;
         i += gridDim.x * blockDim.x) {
        int m  = i >> 6;
        int g8 = i & 63;
        float4 a = v4[m * 128 + g8 * 2];
        float4 b = v4[m * 128 + g8 * 2 + 1];
        float f[8] = {a.x, a.y, a.z, a.w, b.x, b.y, b.z, b.w};
        uint32_t hi[4], lo[4];
#pragma unroll
        for (int j = 0; j < 4; ++j) {
            __nv_bfloat16 h0 = __float2bfloat16(f[2 * j]);
            __nv_bfloat16 h1 = __float2bfloat16(f[2 * j + 1]);
            __nv_bfloat16 l0 = __float2bfloat16(f[2 * j] - __bfloat162float(h0));
            __nv_bfloat16 l1 = __float2bfloat16(f[2 * j + 1] - __bfloat162float(h1));
            __nv_bfloat162 th = __halves2bfloat162(h0, h1);
            __nv_bfloat162 tl = __halves2bfloat162(l0, l1);
            hi[j] = *reinterpret_cast<uint32_t*>(&th);
            lo[j] = *reinterpret_cast<uint32_t*>(&tl);
        }
        int mb = m >> 7, r = m & 127;
        int kc = g8 >> 3, cg = g8 & 7;
        size_t dest = (size_t)(mb * KCH + kc) * TILE_BYTES +
                      sw128((uint32_t)(r * 128 + cg * 16));
        *reinterpret_cast<uint4*>(dhi + dest) = make_uint4(hi[0], hi[1], hi[2], hi[3]);
        *reinterpret_cast<uint4*>(dlo + dest) = make_uint4(lo[0], lo[1], lo[2], lo[3]);
    }
}

// ---------------- kernel 1b: W1 [k][u] -> transposed tiled swizzled ---------
__global__ void convert_w1t(const float* __restrict__ W1) {
    __shared__ float s[32][33];
    const int u0 = blockIdx.x * 32, k0 = blockIdx.y * 32;
    const int tx = threadIdx.x, ty = threadIdx.y;      // (32, 4)
#pragma unroll
    for (int j = 0; j < 8; ++j)
        s[ty + 4 * j][tx] = W1[(size_t)(k0 + ty + 4 * j) * U_ + u0 + tx];
    __syncthreads();
    float f[8];
#pragma unroll
    for (int e = 0; e < 8; ++e) f[e] = s[ty * 8 + e][tx];
    uint32_t hi[4], lo[4];
#pragma unroll
    for (int j = 0; j < 4; ++j) {
        __nv_bfloat16 h0 = __float2bfloat16(f[2 * j]);
        __nv_bfloat16 h1 = __float2bfloat16(f[2 * j + 1]);
        __nv_bfloat16 l0 = __float2bfloat16(f[2 * j] - __bfloat162float(h0));
        __nv_bfloat16 l1 = __float2bfloat16(f[2 * j + 1] - __bfloat162float(h1));
        __nv_bfloat162 th = __halves2bfloat162(h0, h1);
        __nv_bfloat162 tl = __halves2bfloat162(l0, l1);
        hi[j] = *reinterpret_cast<uint32_t*>(&th);
        lo[j] = *reinterpret_cast<uint32_t*>(&tl);
    }
    int u = u0 + tx, kk = k0 + ty * 8;
    int nb = u >> 7, r = u & 127;
    int kc = kk >> 6, cg = (kk & 63) >> 3;
    size_t dest = (size_t)(nb * KCH + kc) * TILE_BYTES +
                  sw128((uint32_t)(r * 128 + cg * 16));
    *reinterpret_cast<uint4*>(reinterpret_cast<char*>(g_w1t_hi) + dest) =
        make_uint4(hi[0], hi[1], hi[2], hi[3]);
    *reinterpret_cast<uint4*>(reinterpret_cast<char*>(g_w1t_lo) + dest) =
        make_uint4(lo[0], lo[1], lo[2], lo[3]);
}

// ---------------- kernel 2: bias partials (split-K, deterministic) ----------
__global__ void bias_part_kernel(const float* __restrict__ q,
                                 const float* __restrict__ W2) {
    const int b = blockIdx.x, ks = blockIdx.y, u = threadIdx.x;
    const float* qb = q + b * D_;
    float acc = 0.f;
#pragma unroll 4
    for (int d = ks * (D_ / KSPLIT); d < (ks + 1) * (D_ / KSPLIT); ++d)
        acc = fmaf(qb[d], W2[(size_t)d * U_ + u], acc);
    g_bias_part[ks][b * U_ + u] = acc;
}

// ---------------- kernel 3: HMMA score GEMM + fused epilogue ----------------
// grid = MB_*NB_ = 2048.  512 threads = 16 warps (wm 0-3 x wn 0-3).
// Warp tile 32x32.  2-stage bulk-copy pipeline, k-loop fully unrolled.
// SMEM: [0..32) mbars (full@s*16, empty@s*16+8), [64..1088) sBV float2[128],
//       [1088..3136) red float[128][4], data @4096: 2 stages x 64KB
//       stage: AH(16K) AL(16K) BH(16K) BL(16K)
#define SM_DATA 4096
#define STG_SZ 65536
#define SMEM_TOTAL (SM_DATA + STAGES * STG_SZ)

__global__ void __launch_bounds__(512, 1)
score_mma_kernel(const float* __restrict__ Vw) {
    extern __shared__ char smem[];
    const uint32_t sb = smem_u32(smem);
    const int tid = threadIdx.x;
    const int lane = tid & 31, wid = tid >> 5;
    const int wm = wid >> 2, wn = wid & 3;

    const int mb = blockIdx.x >> 2;
    const int nb = blockIdx.x & 3;
    const int m0 = mb * 128;
    const int b  = mb >> 4;

    if (tid == 0) {
#pragma unroll
        for (int s = 0; s < STAGES; ++s) {
            MBAR_INIT(sb + s * 16, 1);        // full: expect_tx arrival
            MBAR_INIT(sb + s * 16 + 8, 512);  // empty: all threads
        }
    }
    __syncthreads();

    float2* sBV = reinterpret_cast<float2*>(smem + 64);
    for (int i = tid; i < 128; i += 512) {
        int u = nb * 128 + i;
        float bs = 0.f;
#pragma unroll
        for (int j = 0; j < KSPLIT; ++j) bs += g_bias_part[j][b * U_ + u];
        sBV[i] = make_float2(bs, Vw[u]);
    }

    const char* srcAh = reinterpret_cast<const char*>(g_val_hi) + (size_t)mb * KCH * TILE_BYTES;
    const char* srcAl = reinterpret_cast<const char*>(g_val_lo) + (size_t)mb * KCH * TILE_BYTES;
    const char* srcBh = reinterpret_cast<const char*>(g_w1t_hi) + (size_t)nb * KCH * TILE_BYTES;
    const char* srcBl = reinterpret_cast<const char*>(g_w1t_lo) + (size_t)nb * KCH * TILE_BYTES;

    if (tid == 0) {
#pragma unroll
        for (int c = 0; c < STAGES; ++c) {
            uint32_t st = sb + SM_DATA + c * STG_SZ;
            MBAR_EXPECT_TX(sb + c * 16, 4 * TILE_BYTES);
            BULK_G2S(st,         srcAh + (size_t)c * TILE_BYTES, TILE_BYTES, sb + c * 16);
            BULK_G2S(st + 16384, srcAl + (size_t)c * TILE_BYTES, TILE_BYTES, sb + c * 16);
            BULK_G2S(st + 32768, srcBh + (size_t)c * TILE_BYTES, TILE_BYTES, sb + c * 16);
            BULK_G2S(st + 49152, srcBl + (size_t)c * TILE_BYTES, TILE_BYTES, sb + c * 16);
        }
    }

    // hoisted swizzle components: addr = stage + row*128 + (colbyte ^ xormask)
    uint32_t rowA[2], xmA[2], rowB[2], xmB[2];
#pragma unroll
    for (int mt = 0; mt < 2; ++mt) {
        rowA[mt] = (uint32_t)((wm * 32 + mt * 16 + (lane & 15)) * 128);
        xmA[mt]  = (rowA[mt] >> 3) & 0x70;
    }
#pragma unroll
    for (int p = 0; p < 2; ++p) {
        rowB[p] = (uint32_t)((wn * 32 + p * 16 + (lane & 15)) * 128);
        xmB[p]  = (rowB[p] >> 3) & 0x70;
    }
    const uint32_t hi16 = (uint32_t)(((lane >> 4) & 1) * 16);

    float acc[2][4][4];
#pragma unroll
    for (int mt = 0; mt < 2; ++mt)
#pragma unroll
        for (int nt = 0; nt < 4; ++nt)
#pragma unroll
            for (int e = 0; e < 4; ++e) acc[mt][nt][e] = 0.f;

#pragma unroll
    for (int c = 0; c < KCH; ++c) {
        const int s = c & 1;
        const uint32_t par = (uint32_t)((c >> 1) & 1);
        MBAR_WAIT(sb + s * 16, par);

        const uint32_t aBase = sb + SM_DATA + s * STG_SZ;
        const uint32_t bBase = aBase + 32768;
#pragma unroll
        for (int kk = 0; kk < 4; ++kk) {
            const uint32_t col = (uint32_t)(kk * 32) + hi16;
            uint32_t ah[2][4], al[2][4], bh[4][2], bl[4][2];
#pragma unroll
            for (int mt = 0; mt < 2; ++mt) {
                uint32_t ad = aBase + rowA[mt] + (col ^ xmA[mt]);
                LDSM4(ah[mt], ad);
                LDSM4(al[mt], ad + 16384);
            }
#pragma unroll
            for (int p = 0; p < 2; ++p) {
                uint32_t bd = bBase + rowB[p] + (col ^ xmB[p]);
                uint32_t r[4];
                LDSM4(r, bd);
                bh[2 * p][0] = r[0]; bh[2 * p + 1][0] = r[1];
                bh[2 * p][1] = r[2]; bh[2 * p + 1][1] = r[3];
                LDSM4(r, bd + 16384);
                bl[2 * p][0] = r[0]; bl[2 * p + 1][0] = r[1];
                bl[2 * p][1] = r[2]; bl[2 * p + 1][1] = r[3];
            }
#pragma unroll
            for (int mt = 0; mt < 2; ++mt)
#pragma unroll
                for (int nt = 0; nt < 4; ++nt) {
                    MMA16816(acc[mt][nt], ah[mt], bh[nt]);
                    MMA16816(acc[mt][nt], ah[mt], bl[nt]);
                    MMA16816(acc[mt][nt], al[mt], bh[nt]);
                }
        }
        MBAR_ARRIVE(sb + s * 16 + 8);

        if (tid == 0 && c + STAGES < KCH) {
            MBAR_WAIT(sb + s * 16 + 8, par);
            const int cn = c + STAGES;
            uint32_t st = sb + SM_DATA + s * STG_SZ;
            MBAR_EXPECT_TX(sb + s * 16, 4 * TILE_BYTES);
            BULK_G2S(st,         srcAh + (size_t)cn * TILE_BYTES, TILE_BYTES, sb + s * 16);
            BULK_G2S(st + 16384, srcAl + (size_t)cn * TILE_BYTES, TILE_BYTES, sb + s * 16);
            BULK_G2S(st + 32768, srcBh + (size_t)cn * TILE_BYTES, TILE_BYTES, sb + s * 16);
            BULK_G2S(st + 49152, srcBl + (size_t)cn * TILE_BYTES, TILE_BYTES, sb + s * 16);
        }
    }

    // epilogue: t = V[u]*tanh(c + bias[u]); reduce rows across lanes + wn
    float* red = reinterpret_cast<float*>(smem + 1088);    // [128][4]
#pragma unroll
    for (int mt = 0; mt < 2; ++mt) {
        float p0 = 0.f, p1 = 0.f;
#pragma unroll
        for (int nt = 0; nt < 4; ++nt) {
            int nl = wn * 32 + nt * 8 + 2 * (lane & 3);
            float2 bv0 = sBV[nl], bv1 = sBV[nl + 1];
            p0 = fmaf(bv0.y, tanh_fast(acc[mt][nt][0] + bv0.x), p0);
            p0 = fmaf(bv1.y, tanh_fast(acc[mt][nt][1] + bv1.x), p0);
            p1 = fmaf(bv0.y, tanh_fast(acc[mt][nt][2] + bv0.x), p1);
            p1 = fmaf(bv1.y, tanh_fast(acc[mt][nt][3] + bv1.x), p1);
        }
        p0 += __shfl_xor_sync(0xFFFFFFFFu, p0, 1);
        p0 += __shfl_xor_sync(0xFFFFFFFFu, p0, 2);
        p1 += __shfl_xor_sync(0xFFFFFFFFu, p1, 1);
        p1 += __shfl_xor_sync(0xFFFFFFFFu, p1, 2);
        if ((lane & 3) == 0) {
            int r = wm * 32 + mt * 16 + (lane >> 2);
            red[r * 4 + wn]       = p0;
            red[(r + 8) * 4 + wn] = p1;
        }
    }
    __syncthreads();
    if (tid < 128)
        g_part[nb][m0 + tid] = (red[tid * 4] + red[tid * 4 + 1]) +
                               (red[tid * 4 + 2] + red[tid * 4 + 3]);
}

// ---------------- kernel 4: mask + softmax + argmax + gather ----------------
__global__ void softmax_kernel(const float* __restrict__ value,
                               const int* __restrict__ mask,
                               float* __restrict__ ctx_out,
                               float* __restrict__ a_out) {
    const int b = blockIdx.x;
    const int tid = threadIdx.x;                  // 256
    __shared__ float smax[256];
    __shared__ int   sidx[256];
    __shared__ float ssum[256];
    __shared__ float sc[T_];

    float m = -INFINITY; int mi = T_;
    for (int t = tid; t < T_; t += 256) {
        int i = b * T_ + t;
        float s = g_part[0][i] + g_part[1][i] + g_part[2][i] + g_part[3][i] +
                  (1.f - (float)mask[i]) * -1e20f;
        sc[t] = s;
        if (s > m) { m = s; mi = t; }
    }
    smax[tid] = m; sidx[tid] = mi;
    __syncthreads();
    for (int s = 128; s > 0; s >>= 1) {
        if (tid < s) {
            float om = smax[tid + s]; int oi = sidx[tid + s];
            if (om > smax[tid] || (om == smax[tid] && oi < sidx[tid])) {
                smax[tid] = om; sidx[tid] = oi;
            }
        }
        __syncthreads();
    }
    const float gmax = smax[0];
    const int gidx = sidx[0];

    float sum = 0.f;
    for (int t = tid; t < T_; t += 256) {
        float e = expf(sc[t] - gmax);
        sc[t] = e;
        sum += e;
    }
    ssum[tid] = sum;
    __syncthreads();
    for (int s = 128; s > 0; s >>= 1) {
        if (tid < s) ssum[tid] += ssum[tid + s];
        __syncthreads();
    }
    const float inv = 1.f / ssum[0];

    for (int t = tid; t < T_; t += 256) a_out[b * T_ + t] = sc[t] * inv;
    for (int d = tid; d < D_; d += 256)
        ctx_out[b * D_ + d] = value[((size_t)b * T_ + gidx) * D_ + d];
}

// ---------------------------------------------------------------------------
extern "C" void kernel_launch(void* const* d_in, const int* in_sizes, int n_in,
                              void* d_out, int out_size) {
    const float* value = (const float*)d_in[0];
    const float* query = (const float*)d_in[1];
    const int*   mask  = (const int*)d_in[2];
    const float* W1    = (const float*)d_in[3];
    const float* W2    = (const float*)d_in[4];
    const float* V     = (const float*)d_in[5];

    float* ctx = (float*)d_out;
    float* a   = (float*)d_out + B_ * D_;

    cudaFuncSetAttribute(score_mma_kernel,
                         cudaFuncAttributeMaxDynamicSharedMemorySize, SMEM_TOTAL);

    convert_value<<<2048, 256>>>((const float4*)value);
    convert_w1t<<<dim3(U_ / 32, D_ / 32), dim3(32, 4)>>>(W1);
    bias_part_kernel<<<dim3(B_, KSPLIT), U_>>>(query, W2);
    score_mma_kernel<<<MB_ * NB_, 512, SMEM_TOTAL>>>(V);
    softmax_kernel<<<B_, 256>>>(value, mask, ctx, a);
}

// round 6
// speedup vs baseline: 1.0223x; 1.0223x over previous
#include <cuda_runtime.h>
#include <cuda_bf16.h>
#include <math.h>
#include <stdint.h>

#define B_ 32
#define T_ 2048
#define D_ 512
#define U_ 512
#define MT 65536            // B*T rows
#define MB_ 512             // M blocks of 128
#define NB_ 4               // N blocks of 128
#define KCH 8               // k chunks of 64
#define STAGES 3
#define KSPLIT 8
#define TILE_BYTES 16384    // 128 x 64 bf16
#define GRID_P 148          // persistent CTAs (1 per SM)
#define NTILES (MB_ * NB_)  // 2048

// ---------------- scratch (static device memory only) -----------------------
__device__ __align__(128) __nv_bfloat16 g_val_hi[MT * D_];
__device__ __align__(128) __nv_bfloat16 g_val_lo[MT * D_];
__device__ __align__(128) __nv_bfloat16 g_w1t_hi[U_ * D_];
__device__ __align__(128) __nv_bfloat16 g_w1t_lo[U_ * D_];
__device__ float g_bias_part[KSPLIT][B_ * U_];
__device__ float g_part[NB_][MT];

// ---------------- PTX helpers -----------------------------------------------
__device__ __forceinline__ uint32_t smem_u32(const void* p) {
    uint32_t a;
    asm("{ .reg .u64 t; cvta.to.shared.u64 t, %1; cvt.u32.u64 %0, t; }"
        : "=r"(a) : "l"(p));
    return a;
}
__device__ __forceinline__ uint32_t sw128(uint32_t off) {
    return off ^ ((off >> 3) & 0x70);
}
#define MBAR_INIT(a, n) \
    asm volatile("mbarrier.init.shared.b64 [%0], %1;" :: "r"(a), "r"(n) : "memory")
#define MBAR_ARRIVE(a) \
    asm volatile("mbarrier.arrive.shared.b64 _, [%0];" :: "r"(a) : "memory")
#define MBAR_EXPECT_TX(a, n) \
    asm volatile("mbarrier.arrive.expect_tx.shared.b64 _, [%0], %1;" \
                 :: "r"(a), "r"(n) : "memory")
#define MBAR_WAIT(a, ph) do {                                                  \
    uint32_t _m = (a), _p = (ph), _d;                                          \
    asm volatile("{ .reg .pred p; mbarrier.try_wait.parity.acquire.cta.shared::cta.b64 p, [%1], %2; selp.b32 %0,1,0,p; }" \
                 : "=r"(_d) : "r"(_m), "r"(_p) : "memory");                    \
    if (!_d) {                                                                 \
        asm volatile("{ .reg .pred P1; WL%=: mbarrier.try_wait.parity.acquire.cta.shared::cta.b64 P1, [%0], %1, 0x989680; @P1 bra.uni WD%=; bra.uni WL%=; WD%=: }" \
                     :: "r"(_m), "r"(_p) : "memory");                          \
    }                                                                          \
} while (0)
#define BULK_G2S(dst, src, bytes, mbar)                                        \
    asm volatile("cp.async.bulk.shared::cluster.global.mbarrier::complete_tx::bytes [%0], [%1], %2, [%3];" \
                 :: "r"(dst), "l"(src), "r"(bytes), "r"(mbar) : "memory")
#define LDSM4(r, addr)                                                         \
    asm volatile("ldmatrix.sync.aligned.m8n8.x4.shared.b16 {%0,%1,%2,%3}, [%4];" \
                 : "=r"((r)[0]), "=r"((r)[1]), "=r"((r)[2]), "=r"((r)[3])      \
                 : "r"(addr))
#define MMA16816(d, a, b)                                                      \
    asm volatile("mma.sync.aligned.m16n8k16.row.col.f32.bf16.bf16.f32 "        \
                 "{%0,%1,%2,%3}, {%4,%5,%6,%7}, {%8,%9}, {%0,%1,%2,%3};"       \
                 : "+f"((d)[0]), "+f"((d)[1]), "+f"((d)[2]), "+f"((d)[3])      \
                 : "r"((a)[0]), "r"((a)[1]), "r"((a)[2]), "r"((a)[3]),         \
                   "r"((b)[0]), "r"((b)[1]))

// tanh via exp: abs err ~1e-6; saturates correctly for large |x|
__device__ __forceinline__ float tanh_fast(float x) {
    float z = __expf(2.0f * x);
    return 1.0f - __fdividef(2.0f, z + 1.0f);
}

// ---------------- kernel 1a: value fp32 -> tiled swizzled bf16 hi/lo --------
__global__ void convert_value(const float4* __restrict__ v4) {
    char* dhi = reinterpret_cast<char*>(g_val_hi);
    char* dlo = reinterpret_cast<char*>(g_val_lo);
    const int ngran = MT * D_ / 8;
    for (int i = blockIdx.x * blockDim.x + threadIdx.x; i < ngran;
         i += gridDim.x * blockDim.x) {
        int m  = i >> 6;
        int g8 = i & 63;
        float4 a = v4[m * 128 + g8 * 2];
        float4 b = v4[m * 128 + g8 * 2 + 1];
        float f[8] = {a.x, a.y, a.z, a.w, b.x, b.y, b.z, b.w};
        uint32_t hi[4], lo[4];
#pragma unroll
        for (int j = 0; j < 4; ++j) {
            __nv_bfloat16 h0 = __float2bfloat16(f[2 * j]);
            __nv_bfloat16 h1 = __float2bfloat16(f[2 * j + 1]);
            __nv_bfloat16 l0 = __float2bfloat16(f[2 * j] - __bfloat162float(h0));
            __nv_bfloat16 l1 = __float2bfloat16(f[2 * j + 1] - __bfloat162float(h1));
            __nv_bfloat162 th = __halves2bfloat162(h0, h1);
            __nv_bfloat162 tl = __halves2bfloat162(l0, l1);
            hi[j] = *reinterpret_cast<uint32_t*>(&th);
            lo[j] = *reinterpret_cast<uint32_t*>(&tl);
        }
        int mb = m >> 7, r = m & 127;
        int kc = g8 >> 3, cg = g8 & 7;
        size_t dest = (size_t)(mb * KCH + kc) * TILE_BYTES +
                      sw128((uint32_t)(r * 128 + cg * 16));
        *reinterpret_cast<uint4*>(dhi + dest) = make_uint4(hi[0], hi[1], hi[2], hi[3]);
        *reinterpret_cast<uint4*>(dlo + dest) = make_uint4(lo[0], lo[1], lo[2], lo[3]);
    }
}

// ---------------- kernel 1b: W1 [k][u] -> transposed tiled swizzled ---------
__global__ void convert_w1t(const float* __restrict__ W1) {
    __shared__ float s[32][33];
    const int u0 = blockIdx.x * 32, k0 = blockIdx.y * 32;
    const int tx = threadIdx.x, ty = threadIdx.y;      // (32, 4)
#pragma unroll
    for (int j = 0; j < 8; ++j)
        s[ty + 4 * j][tx] = W1[(size_t)(k0 + ty + 4 * j) * U_ + u0 + tx];
    __syncthreads();
    float f[8];
#pragma unroll
    for (int e = 0; e < 8; ++e) f[e] = s[ty * 8 + e][tx];
    uint32_t hi[4], lo[4];
#pragma unroll
    for (int j = 0; j < 4; ++j) {
        __nv_bfloat16 h0 = __float2bfloat16(f[2 * j]);
        __nv_bfloat16 h1 = __float2bfloat16(f[2 * j + 1]);
        __nv_bfloat16 l0 = __float2bfloat16(f[2 * j] - __bfloat162float(h0));
        __nv_bfloat16 l1 = __float2bfloat16(f[2 * j + 1] - __bfloat162float(h1));
        __nv_bfloat162 th = __halves2bfloat162(h0, h1);
        __nv_bfloat162 tl = __halves2bfloat162(l0, l1);
        hi[j] = *reinterpret_cast<uint32_t*>(&th);
        lo[j] = *reinterpret_cast<uint32_t*>(&tl);
    }
    int u = u0 + tx, kk = k0 + ty * 8;
    int nb = u >> 7, r = u & 127;
    int kc = kk >> 6, cg = (kk & 63) >> 3;
    size_t dest = (size_t)(nb * KCH + kc) * TILE_BYTES +
                  sw128((uint32_t)(r * 128 + cg * 16));
    *reinterpret_cast<uint4*>(reinterpret_cast<char*>(g_w1t_hi) + dest) =
        make_uint4(hi[0], hi[1], hi[2], hi[3]);
    *reinterpret_cast<uint4*>(reinterpret_cast<char*>(g_w1t_lo) + dest) =
        make_uint4(lo[0], lo[1], lo[2], lo[3]);
}

// ---------------- kernel 2: bias partials (split-K, deterministic) ----------
__global__ void bias_part_kernel(const float* __restrict__ q,
                                 const float* __restrict__ W2) {
    const int b = blockIdx.x, ks = blockIdx.y, u = threadIdx.x;
    const float* qb = q + b * D_;
    float acc = 0.f;
#pragma unroll 4
    for (int d = ks * (D_ / KSPLIT); d < (ks + 1) * (D_ / KSPLIT); ++d)
        acc = fmaf(qb[d], W2[(size_t)d * U_ + u], acc);
    g_bias_part[ks][b * U_ + u] = acc;
}

// ---------------- kernel 3: persistent HMMA GEMM + fused epilogue -----------
// grid = 148 (1 CTA/SM).  512 threads = 16 warps (wm 0-3 x wn 0-3), warp tile
// 32x32.  CTA loops tiles bid, bid+148, ... ; 3-stage bulk-copy pipeline runs
// continuously across tiles (chunk counter cc spans tiles).
// SMEM: [0..48) mbars (full@s*16, empty@s*16+8), [64..1088) sBV float2[128],
//       [1088..3136) red float[128][4], data @4096: 3 stages x 64KB
#define SM_DATA 4096
#define STG_SZ 65536
#define SMEM_TOTAL (SM_DATA + STAGES * STG_SZ)

// chunk cc (flattened tile-major) -> 4 bulk copies into stage cc%STAGES
static __device__ __forceinline__ void produce_chunk(uint32_t sb, int bid, int cc) {
    const int t  = bid + (cc >> 3) * GRID_P;
    const int mb = t >> 2, nb = t & 3, c = cc & 7;
    const int s  = cc % STAGES;
    const uint32_t st = sb + SM_DATA + s * STG_SZ;
    const size_t offA = (size_t)(mb * KCH + c) * TILE_BYTES;
    const size_t offB = (size_t)(nb * KCH + c) * TILE_BYTES;
    MBAR_EXPECT_TX(sb + s * 16, 4 * TILE_BYTES);
    BULK_G2S(st,         reinterpret_cast<const char*>(g_val_hi) + offA, TILE_BYTES, sb + s * 16);
    BULK_G2S(st + 16384, reinterpret_cast<const char*>(g_val_lo) + offA, TILE_BYTES, sb + s * 16);
    BULK_G2S(st + 32768, reinterpret_cast<const char*>(g_w1t_hi) + offB, TILE_BYTES, sb + s * 16);
    BULK_G2S(st + 49152, reinterpret_cast<const char*>(g_w1t_lo) + offB, TILE_BYTES, sb + s * 16);
}

__global__ void __launch_bounds__(512, 1)
score_mma_kernel(const float* __restrict__ Vw) {
    extern __shared__ char smem[];
    const uint32_t sb = smem_u32(smem);
    const int tid = threadIdx.x;
    const int lane = tid & 31, wid = tid >> 5;
    const int wm = wid >> 2, wn = wid & 3;
    const int bid = blockIdx.x;

    const int ntiles  = (NTILES - bid + GRID_P - 1) / GRID_P;
    const int totalcc = ntiles * KCH;

    if (tid == 0) {
#pragma unroll
        for (int s = 0; s < STAGES; ++s) {
            MBAR_INIT(sb + s * 16, 1);        // full: expect_tx arrival
            MBAR_INIT(sb + s * 16 + 8, 16);   // empty: one lane per warp
        }
    }
    __syncthreads();

    if (tid == 0) {
#pragma unroll
        for (int c = 0; c < STAGES; ++c)
            if (c < totalcc) produce_chunk(sb, bid, c);
    }

    // hoisted swizzle components: addr = stage + row*128 + (colbyte ^ xormask)
    uint32_t rowA[2], xmA[2], rowB[2], xmB[2];
#pragma unroll
    for (int mt = 0; mt < 2; ++mt) {
        rowA[mt] = (uint32_t)((wm * 32 + mt * 16 + (lane & 15)) * 128);
        xmA[mt]  = (rowA[mt] >> 3) & 0x70;
    }
#pragma unroll
    for (int p = 0; p < 2; ++p) {
        rowB[p] = (uint32_t)((wn * 32 + p * 16 + (lane & 15)) * 128);
        xmB[p]  = (rowB[p] >> 3) & 0x70;
    }
    const uint32_t hi16 = (uint32_t)(((lane >> 4) & 1) * 16);

    float2* sBV = reinterpret_cast<float2*>(smem + 64);
    float* red  = reinterpret_cast<float*>(smem + 1088);   // [128][4]

    int cc = 0;
    for (int j = 0; j < ntiles; ++j) {
        const int t  = bid + j * GRID_P;
        const int mb = t >> 2, nb = t & 3;
        const int m0 = mb * 128;
        const int b  = mb >> 4;

        // per-tile epilogue constants (sync at loop bottom protects reuse)
        for (int i = tid; i < 128; i += 512) {
            int u = nb * 128 + i;
            float bs = 0.f;
#pragma unroll
            for (int jj = 0; jj < KSPLIT; ++jj) bs += g_bias_part[jj][b * U_ + u];
            sBV[i] = make_float2(bs, Vw[u]);
        }
        __syncthreads();

        float acc[2][4][4];
#pragma unroll
        for (int mt = 0; mt < 2; ++mt)
#pragma unroll
            for (int nt = 0; nt < 4; ++nt)
#pragma unroll
                for (int e = 0; e < 4; ++e) acc[mt][nt][e] = 0.f;

#pragma unroll
        for (int c = 0; c < KCH; ++c, ++cc) {
            const int s = cc % STAGES;
            const uint32_t par = (uint32_t)((cc / STAGES) & 1);
            MBAR_WAIT(sb + s * 16, par);

            const uint32_t aBase = sb + SM_DATA + s * STG_SZ;
            const uint32_t bBase = aBase + 32768;
#pragma unroll
            for (int kk = 0; kk < 4; ++kk) {
                const uint32_t col = (uint32_t)(kk * 32) + hi16;
                uint32_t ah[2][4], al[2][4], bh[4][2], bl[4][2];
#pragma unroll
                for (int mt = 0; mt < 2; ++mt) {
                    uint32_t ad = aBase + rowA[mt] + (col ^ xmA[mt]);
                    LDSM4(ah[mt], ad);
                    LDSM4(al[mt], ad + 16384);
                }
#pragma unroll
                for (int p = 0; p < 2; ++p) {
                    uint32_t bd = bBase + rowB[p] + (col ^ xmB[p]);
                    uint32_t r[4];
                    LDSM4(r, bd);
                    bh[2 * p][0] = r[0]; bh[2 * p + 1][0] = r[1];
                    bh[2 * p][1] = r[2]; bh[2 * p + 1][1] = r[3];
                    LDSM4(r, bd + 16384);
                    bl[2 * p][0] = r[0]; bl[2 * p + 1][0] = r[1];
                    bl[2 * p][1] = r[2]; bl[2 * p + 1][1] = r[3];
                }
#pragma unroll
                for (int mt = 0; mt < 2; ++mt)
#pragma unroll
                    for (int nt = 0; nt < 4; ++nt) {
                        MMA16816(acc[mt][nt], ah[mt], bh[nt]);
                        MMA16816(acc[mt][nt], ah[mt], bl[nt]);
                        MMA16816(acc[mt][nt], al[mt], bh[nt]);
                    }
            }
            if (lane == 0) MBAR_ARRIVE(sb + s * 16 + 8);

            if (tid == 0 && cc + STAGES < totalcc) {
                MBAR_WAIT(sb + s * 16 + 8, par);       // stage drained by all warps
                produce_chunk(sb, bid, cc + STAGES);
            }
        }

        // epilogue: V[u]*tanh(c + bias[u]); reduce across lanes + wn
#pragma unroll
        for (int mt = 0; mt < 2; ++mt) {
            float p0 = 0.f, p1 = 0.f;
#pragma unroll
            for (int nt = 0; nt < 4; ++nt) {
                int nl = wn * 32 + nt * 8 + 2 * (lane & 3);
                float2 bv0 = sBV[nl], bv1 = sBV[nl + 1];
                p0 = fmaf(bv0.y, tanh_fast(acc[mt][nt][0] + bv0.x), p0);
                p0 = fmaf(bv1.y, tanh_fast(acc[mt][nt][1] + bv1.x), p0);
                p1 = fmaf(bv0.y, tanh_fast(acc[mt][nt][2] + bv0.x), p1);
                p1 = fmaf(bv1.y, tanh_fast(acc[mt][nt][3] + bv1.x), p1);
            }
            p0 += __shfl_xor_sync(0xFFFFFFFFu, p0, 1);
            p0 += __shfl_xor_sync(0xFFFFFFFFu, p0, 2);
            p1 += __shfl_xor_sync(0xFFFFFFFFu, p1, 1);
            p1 += __shfl_xor_sync(0xFFFFFFFFu, p1, 2);
            if ((lane & 3) == 0) {
                int r = wm * 32 + mt * 16 + (lane >> 2);
                red[r * 4 + wn]       = p0;
                red[(r + 8) * 4 + wn] = p1;
            }
        }
        __syncthreads();
        if (tid < 128)
            g_part[nb][m0 + tid] = (red[tid * 4] + red[tid * 4 + 1]) +
                                   (red[tid * 4 + 2] + red[tid * 4 + 3]);
        __syncthreads();   // protect red/sBV before next tile overwrites
    }
}

// ---------------- kernel 4: mask + softmax + argmax + gather ----------------
__global__ void softmax_kernel(const float* __restrict__ value,
                               const int* __restrict__ mask,
                               float* __restrict__ ctx_out,
                               float* __restrict__ a_out) {
    const int b = blockIdx.x;
    const int tid = threadIdx.x;                  // 256
    __shared__ float smax[256];
    __shared__ int   sidx[256];
    __shared__ float ssum[256];
    __shared__ float sc[T_];

    float m = -INFINITY; int mi = T_;
    for (int t = tid; t < T_; t += 256) {
        int i = b * T_ + t;
        float s = g_part[0][i] + g_part[1][i] + g_part[2][i] + g_part[3][i] +
                  (1.f - (float)mask[i]) * -1e20f;
        sc[t] = s;
        if (s > m) { m = s; mi = t; }
    }
    smax[tid] = m; sidx[tid] = mi;
    __syncthreads();
    for (int s = 128; s > 0; s >>= 1) {
        if (tid < s) {
            float om = smax[tid + s]; int oi = sidx[tid + s];
            if (om > smax[tid] || (om == smax[tid] && oi < sidx[tid])) {
                smax[tid] = om; sidx[tid] = oi;
            }
        }
        __syncthreads();
    }
    const float gmax = smax[0];
    const int gidx = sidx[0];

    float sum = 0.f;
    for (int t = tid; t < T_; t += 256) {
        float e = expf(sc[t] - gmax);
        sc[t] = e;
        sum += e;
    }
    ssum[tid] = sum;
    __syncthreads();
    for (int s = 128; s > 0; s >>= 1) {
        if (tid < s) ssum[tid] += ssum[tid + s];
        __syncthreads();
    }
    const float inv = 1.f / ssum[0];

    for (int t = tid; t < T_; t += 256) a_out[b * T_ + t] = sc[t] * inv;
    for (int d = tid; d < D_; d += 256)
        ctx_out[b * D_ + d] = value[((size_t)b * T_ + gidx) * D_ + d];
}

// ---------------------------------------------------------------------------
extern "C" void kernel_launch(void* const* d_in, const int* in_sizes, int n_in,
                              void* d_out, int out_size) {
    const float* value = (const float*)d_in[0];
    const float* query = (const float*)d_in[1];
    const int*   mask  = (const int*)d_in[2];
    const float* W1    = (const float*)d_in[3];
    const float* W2    = (const float*)d_in[4];
    const float* V     = (const float*)d_in[5];

    float* ctx = (float*)d_out;
    float* a   = (float*)d_out + B_ * D_;

    cudaFuncSetAttribute(score_mma_kernel,
                         cudaFuncAttributeMaxDynamicSharedMemorySize, SMEM_TOTAL);

    convert_value<<<2048, 256>>>((const float4*)value);
    convert_w1t<<<dim3(U_ / 32, D_ / 32), dim3(32, 4)>>>(W1);
    bias_part_kernel<<<dim3(B_, KSPLIT), U_>>>(query, W2);
    score_mma_kernel<<<GRID_P, 512, SMEM_TOTAL>>>(V);
    softmax_kernel<<<B_, 256>>>(value, mask, ctx, a);
}